// round 6
// baseline (speedup 1.0000x reference)
#include <cuda_runtime.h>
#include <cstdint>

// out[b,t,a] = start_state[b,a] + (t/255) * patterns[iid[b], t, a]
// B=256, T=256, AD=64.
//
// R6: full bulk-async pipeline. Per CTA (1024 CTAs): TMA-load a 16KB pattern
// chunk into smem, transform IN PLACE (each thread overwrites exactly the
// float4 it read), then emit with ONE cp.async.bulk shared->global TMA store.
// Output bytes never touch the per-warp STG path.

#define B_   256
#define T_   256
#define AD_  64
#define TPB  256
#define CHUNK_T 64
#define CHUNK_F4 (CHUNK_T * 16)            // 1024 float4
#define CHUNK_BYTES (CHUNK_T * AD_ * 4)    // 16384

__global__ __launch_bounds__(TPB)
void traj_kernel(const float* __restrict__ start_state,    // [B, 64]
                 const int*   __restrict__ instruction_id, // [B]
                 const float* __restrict__ patterns,       // [V, T, 64]
                 float*       __restrict__ out)            // [B, T, 64]
{
    __shared__ alignas(128) float buf[CHUNK_T * AD_];      // 16 KB
    __shared__ alignas(8) unsigned long long mbar;

    const unsigned bid   = blockIdx.x;
    const unsigned b     = bid >> 2;
    const unsigned chunk = bid & 3u;
    const unsigned tid   = threadIdx.x;

    const uint32_t mbar_addr = (uint32_t)__cvta_generic_to_shared(&mbar);
    const uint32_t buf_addr  = (uint32_t)__cvta_generic_to_shared(buf);

    if (tid == 0) {
        asm volatile("mbarrier.init.shared.b64 [%0], 1;"
                     :: "r"(mbar_addr) : "memory");
        asm volatile("fence.proxy.async.shared::cta;" ::: "memory");
    }
    __syncthreads();

    if (tid == 0) {
        const int iid = __ldg(&instruction_id[b]);
        const float* src = patterns + ((size_t)iid * T_ + (size_t)chunk * CHUNK_T) * AD_;
        asm volatile("mbarrier.arrive.expect_tx.shared.b64 _, [%0], %1;"
                     :: "r"(mbar_addr), "r"((unsigned)CHUNK_BYTES) : "memory");
        asm volatile("cp.async.bulk.shared::cta.global.mbarrier::complete_tx::bytes "
                     "[%0], [%1], %2, [%3];"
                     :: "r"(buf_addr), "l"(src), "r"((unsigned)CHUNK_BYTES), "r"(mbar_addr)
                     : "memory");
    }

    // Overlap: invariant per-thread state.
    const unsigned a4 = tid & 15u;        // float4 slot within 64-float row
    const float4 s = __ldg((const float4*)(start_state + (size_t)b * AD_) + a4);

    // Wait for the bulk load (acquire orders smem reads).
    {
        uint32_t done;
        asm volatile(
            "{\n\t"
            ".reg .pred p;\n\t"
            "mbarrier.try_wait.parity.acquire.cta.shared::cta.b64 p, [%1], %2;\n\t"
            "selp.b32 %0, 1, 0, p;\n\t"
            "}"
            : "=r"(done) : "r"(mbar_addr), "r"(0u) : "memory");
        if (!done) {
            asm volatile(
                "{\n\t"
                ".reg .pred P1;\n\t"
                "WAIT_LOOP_%=:\n\t"
                "mbarrier.try_wait.parity.acquire.cta.shared::cta.b64 P1, [%0], %1, 0x989680;\n\t"
                "@P1 bra.uni WAIT_DONE_%=;\n\t"
                "bra.uni WAIT_LOOP_%=;\n\t"
                "WAIT_DONE_%=:\n\t"
                "}"
                :: "r"(mbar_addr), "r"(0u) : "memory");
        }
    }

    // In-place transform: thread handles f4 indices tid + k*256, k=0..3.
    // a4 = (tid + k*256) & 15 == tid & 15 for all k (256 % 16 == 0).
    float4* __restrict__ sb = (float4*)buf;
#pragma unroll
    for (int k = 0; k < 4; k++) {
        const unsigned j  = tid + (unsigned)k * TPB;    // 0..1023
        const unsigned tl = j >> 4;                     // local t 0..63
        const float prog = (float)(chunk * CHUNK_T + tl) * (1.0f / (float)(T_ - 1));
        float4 p = sb[j];
        p.x = fmaf(prog, p.x, s.x);
        p.y = fmaf(prog, p.y, s.y);
        p.z = fmaf(prog, p.z, s.z);
        p.w = fmaf(prog, p.w, s.w);
        sb[j] = p;
    }

    __syncthreads();

    if (tid == 0) {
        // Make generic-proxy smem writes visible to the async proxy.
        asm volatile("fence.proxy.async.shared::cta;" ::: "memory");
        float* dst = out + ((size_t)b * T_ + (size_t)chunk * CHUNK_T) * AD_;
        asm volatile("cp.async.bulk.global.shared::cta.bulk_group [%0], [%1], %2;"
                     :: "l"(dst), "r"(buf_addr), "r"((unsigned)CHUNK_BYTES)
                     : "memory");
        asm volatile("cp.async.bulk.commit_group;" ::: "memory");
        asm volatile("cp.async.bulk.wait_group 0;" ::: "memory");
    }
}

extern "C" void kernel_launch(void* const* d_in, const int* in_sizes, int n_in,
                              void* d_out, int out_size)
{
    const float* start_state    = (const float*)d_in[0];
    const int*   instruction_id = (const int*)  d_in[1];
    const float* patterns       = (const float*)d_in[27];
    float*       out            = (float*)d_out;

    traj_kernel<<<B_ * 4, TPB>>>(start_state, instruction_id, patterns, out);
}